// round 3
// baseline (speedup 1.0000x reference)
#include <cuda_runtime.h>
#include <cuda_bf16.h>
#include <stdint.h>

#define Nn 100000
#define Ee 1600000
#define Gg 512
#define Hh 128
#define NB_SCAN ((Nn + 1023) / 1024)   /* 98 */
#define CDIV(a,b) (((a)+(b)-1)/(b))

// ---------------- scratch (static device globals; no runtime alloc) ----------------
__device__ __align__(16) float g_hA[(size_t)Nn * Hh];
__device__ __align__(16) float g_hB[(size_t)Nn * Hh];
__device__ __align__(16) float g_agg[(size_t)Nn * Hh];
__device__ float g_norm_out[Nn];
__device__ float g_norm_in[Nn];
__device__ int   g_outdeg[Nn];
__device__ int   g_indeg[Nn];
__device__ int   g_cursor[Nn];
__device__ int   g_rowstart[Nn + 1];
__device__ int   g_esrc[Ee];
__device__ int   g_partials[128];
__device__ int   g_partoff[128];
__device__ __align__(16) float g_gsum[Gg * Hh];

// ---------------- init: zero counters + readout buffer ----------------
__global__ void init_kernel() {
    int i = blockIdx.x * blockDim.x + threadIdx.x;
    if (i < Nn) { g_indeg[i] = 0; g_outdeg[i] = 0; g_cursor[i] = 0; }
    if (i < Gg * Hh) g_gsum[i] = 0.0f;
}

// ---------------- degrees ----------------
__global__ void degree_kernel(const int* __restrict__ src, const int* __restrict__ dst) {
    int e = blockIdx.x * blockDim.x + threadIdx.x;
    if (e >= Ee) return;
    atomicAdd(&g_outdeg[src[e]], 1);
    atomicAdd(&g_indeg[dst[e]], 1);
}

__global__ void norm_kernel() {
    int i = blockIdx.x * blockDim.x + threadIdx.x;
    if (i >= Nn) return;
    g_norm_out[i] = rsqrtf(fmaxf((float)g_outdeg[i], 1.0f));
    g_norm_in[i]  = rsqrtf(fmaxf((float)g_indeg[i], 1.0f));
}

// ---------------- exclusive scan of indeg -> rowstart ----------------
__global__ void scan_block_kernel() {
    __shared__ int sh[1024];
    int tid = threadIdx.x;
    int idx = blockIdx.x * 1024 + tid;
    int v = (idx < Nn) ? g_indeg[idx] : 0;
    sh[tid] = v;
    __syncthreads();
    #pragma unroll
    for (int off = 1; off < 1024; off <<= 1) {
        int t = 0;
        if (tid >= off) t = sh[tid - off];
        __syncthreads();
        if (tid >= off) sh[tid] += t;
        __syncthreads();
    }
    if (idx < Nn) g_rowstart[idx] = sh[tid] - v;   // exclusive within block
    if (tid == 1023) g_partials[blockIdx.x] = sh[1023];
}

__global__ void scan_partials_kernel() {
    __shared__ int sh[128];
    int t = threadIdx.x;
    int v = (t < NB_SCAN) ? g_partials[t] : 0;
    sh[t] = v;
    __syncthreads();
    #pragma unroll
    for (int off = 1; off < 128; off <<= 1) {
        int x = 0;
        if (t >= off) x = sh[t - off];
        __syncthreads();
        if (t >= off) sh[t] += x;
        __syncthreads();
    }
    g_partoff[t] = sh[t] - v;   // exclusive block offsets
}

__global__ void add_off_kernel() {
    int i = blockIdx.x * blockDim.x + threadIdx.x;
    if (i < Nn) g_rowstart[i] += g_partoff[i >> 10];
    if (i == 0) g_rowstart[Nn] = Ee;
}

// ---------------- bucket edges by dst ----------------
__global__ void bucket_kernel(const int* __restrict__ src, const int* __restrict__ dst) {
    int e = blockIdx.x * blockDim.x + threadIdx.x;
    if (e >= Ee) return;
    int d = dst[e];
    int pos = g_rowstart[d] + atomicAdd(&g_cursor[d], 1);
    g_esrc[pos] = src[e];
}

// ---------------- aggregation: warp per node, pure gather ----------------
__global__ void agg_kernel(const float* __restrict__ hin, float* __restrict__ hout) {
    int w = (blockIdx.x * blockDim.x + threadIdx.x) >> 5;
    int lane = threadIdx.x & 31;
    if (w >= Nn) return;
    int beg = g_rowstart[w], end = g_rowstart[w + 1];
    float4 acc = make_float4(0.f, 0.f, 0.f, 0.f);
    for (int e = beg; e < end; e++) {
        int s = g_esrc[e];
        float no = g_norm_out[s];
        float4 v = reinterpret_cast<const float4*>(hin + (size_t)s * Hh)[lane];
        acc.x += no * v.x; acc.y += no * v.y; acc.z += no * v.z; acc.w += no * v.w;
    }
    float ni = g_norm_in[w];
    acc.x *= ni; acc.y *= ni; acc.z *= ni; acc.w *= ni;
    reinterpret_cast<float4*>(hout + (size_t)w * Hh)[lane] = acc;
}

// ---------------- GEMM + bias + ReLU: C[N,128] = relu(A @ W + b) ----------------
// BM=64 rows per block, full K=128 & Ncols=128. 256 threads, 4x8 microtile.
#define BM 64
#define ASM_STRIDE 65
__global__ void gemm_relu_kernel(const float* __restrict__ A, const float* __restrict__ W,
                                 const float* __restrict__ bias, float* __restrict__ C) {
    extern __shared__ float sm[];
    float* Wsm = sm;                 // [128*128]
    float* Asm = sm + 128 * 128;     // [128][ASM_STRIDE] transposed (k-major)
    int tid = threadIdx.x;
    int row0 = blockIdx.x * BM;

    // stage W (16384 floats) via float4
    const float4* W4 = reinterpret_cast<const float4*>(W);
    float4* Wsm4 = reinterpret_cast<float4*>(Wsm);
    #pragma unroll
    for (int i = 0; i < 16; i++) Wsm4[tid + 256 * i] = W4[tid + 256 * i];

    // stage A tile transposed: 64 rows x 128 cols
    #pragma unroll
    for (int i = 0; i < 8; i++) {
        int idx = tid + 256 * i;            // 0..2047
        int r = idx >> 5, c4 = idx & 31;
        int grow = row0 + r;
        float4 v = make_float4(0.f, 0.f, 0.f, 0.f);
        if (grow < Nn) v = reinterpret_cast<const float4*>(A + (size_t)grow * Hh)[c4];
        int k = c4 * 4;
        Asm[(k + 0) * ASM_STRIDE + r] = v.x;
        Asm[(k + 1) * ASM_STRIDE + r] = v.y;
        Asm[(k + 2) * ASM_STRIDE + r] = v.z;
        Asm[(k + 3) * ASM_STRIDE + r] = v.w;
    }
    __syncthreads();

    int cg = tid & 15;    // column group: cols cg*8 .. cg*8+7
    int rg = tid >> 4;    // row group: rows rg*4 .. rg*4+3
    float acc[4][8];
    #pragma unroll
    for (int i = 0; i < 4; i++)
        #pragma unroll
        for (int j = 0; j < 8; j++) acc[i][j] = 0.f;

    const float4* Wr = reinterpret_cast<const float4*>(Wsm);
    #pragma unroll 8
    for (int k = 0; k < 128; k++) {
        float a0 = Asm[k * ASM_STRIDE + rg * 4 + 0];
        float a1 = Asm[k * ASM_STRIDE + rg * 4 + 1];
        float a2 = Asm[k * ASM_STRIDE + rg * 4 + 2];
        float a3 = Asm[k * ASM_STRIDE + rg * 4 + 3];
        float4 w0 = Wr[k * 32 + cg * 2];
        float4 w1 = Wr[k * 32 + cg * 2 + 1];
        acc[0][0] += a0 * w0.x; acc[0][1] += a0 * w0.y; acc[0][2] += a0 * w0.z; acc[0][3] += a0 * w0.w;
        acc[0][4] += a0 * w1.x; acc[0][5] += a0 * w1.y; acc[0][6] += a0 * w1.z; acc[0][7] += a0 * w1.w;
        acc[1][0] += a1 * w0.x; acc[1][1] += a1 * w0.y; acc[1][2] += a1 * w0.z; acc[1][3] += a1 * w0.w;
        acc[1][4] += a1 * w1.x; acc[1][5] += a1 * w1.y; acc[1][6] += a1 * w1.z; acc[1][7] += a1 * w1.w;
        acc[2][0] += a2 * w0.x; acc[2][1] += a2 * w0.y; acc[2][2] += a2 * w0.z; acc[2][3] += a2 * w0.w;
        acc[2][4] += a2 * w1.x; acc[2][5] += a2 * w1.y; acc[2][6] += a2 * w1.z; acc[2][7] += a2 * w1.w;
        acc[3][0] += a3 * w0.x; acc[3][1] += a3 * w0.y; acc[3][2] += a3 * w0.z; acc[3][3] += a3 * w0.w;
        acc[3][4] += a3 * w1.x; acc[3][5] += a3 * w1.y; acc[3][6] += a3 * w1.z; acc[3][7] += a3 * w1.w;
    }

    float4 bb0 = reinterpret_cast<const float4*>(bias)[cg * 2];
    float4 bb1 = reinterpret_cast<const float4*>(bias)[cg * 2 + 1];
    #pragma unroll
    for (int i = 0; i < 4; i++) {
        int grow = row0 + rg * 4 + i;
        if (grow >= Nn) continue;
        float4 o0, o1;
        o0.x = fmaxf(acc[i][0] + bb0.x, 0.f); o0.y = fmaxf(acc[i][1] + bb0.y, 0.f);
        o0.z = fmaxf(acc[i][2] + bb0.z, 0.f); o0.w = fmaxf(acc[i][3] + bb0.w, 0.f);
        o1.x = fmaxf(acc[i][4] + bb1.x, 0.f); o1.y = fmaxf(acc[i][5] + bb1.y, 0.f);
        o1.z = fmaxf(acc[i][6] + bb1.z, 0.f); o1.w = fmaxf(acc[i][7] + bb1.w, 0.f);
        float4* Crow = reinterpret_cast<float4*>(C + (size_t)grow * Hh);
        Crow[cg * 2] = o0; Crow[cg * 2 + 1] = o1;
    }
}

// ---------------- readout: warp per 16 consecutive nodes, run-batched atomics ----------------
__global__ void readout_kernel(const float* __restrict__ h, const int* __restrict__ n2g) {
    int w = (blockIdx.x * blockDim.x + threadIdx.x) >> 5;
    int lane = threadIdx.x & 31;
    int n0 = w * 16;
    if (n0 >= Nn) return;
    int n1 = min(n0 + 16, Nn);
    float4 acc = make_float4(0.f, 0.f, 0.f, 0.f);
    int curg = n2g[n0];
    for (int v = n0; v < n1; v++) {
        int gid = n2g[v];
        if (gid != curg) {
            float* base = &g_gsum[curg * Hh + lane * 4];
            atomicAdd(base + 0, acc.x); atomicAdd(base + 1, acc.y);
            atomicAdd(base + 2, acc.z); atomicAdd(base + 3, acc.w);
            acc = make_float4(0.f, 0.f, 0.f, 0.f);
            curg = gid;
        }
        float4 xv = reinterpret_cast<const float4*>(h + (size_t)v * Hh)[lane];
        acc.x += xv.x; acc.y += xv.y; acc.z += xv.z; acc.w += xv.w;
    }
    float* base = &g_gsum[curg * Hh + lane * 4];
    atomicAdd(base + 0, acc.x); atomicAdd(base + 1, acc.y);
    atomicAdd(base + 2, acc.z); atomicAdd(base + 3, acc.w);
}

// ---------------- MLP head: relu(g @ Wm1 + bm1) @ Wm2 + bm2 ----------------
__global__ void mlp_kernel(const float* __restrict__ Wm1, const float* __restrict__ bm1,
                           const float* __restrict__ Wm2, const float* __restrict__ bm2,
                           float* __restrict__ out) {
    __shared__ float grow[Hh];
    __shared__ float red[Hh];
    int b = blockIdx.x, t = threadIdx.x;
    grow[t] = g_gsum[b * Hh + t];
    __syncthreads();
    float acc = 0.f;
    #pragma unroll
    for (int k = 0; k < Hh; k++) acc += grow[k] * Wm1[k * Hh + t];
    acc = fmaxf(acc + bm1[t], 0.f);
    red[t] = acc * Wm2[t];
    __syncthreads();
    #pragma unroll
    for (int s = 64; s > 0; s >>= 1) {
        if (t < s) red[t] += red[t + s];
        __syncthreads();
    }
    if (t == 0) out[b] = red[0] + bm2[0];
}

// ---------------- launch ----------------
extern "C" void kernel_launch(void* const* d_in, const int* in_sizes, int n_in,
                              void* d_out, int out_size) {
    const float* x   = (const float*)d_in[0];
    const int*   src = (const int*)d_in[1];
    const int*   dst = (const int*)d_in[2];
    const int*   n2g = (const int*)d_in[3];
    const float* W0  = (const float*)d_in[4];
    const float* b0  = (const float*)d_in[5];
    const float* W1  = (const float*)d_in[6];
    const float* b1  = (const float*)d_in[7];
    const float* W2  = (const float*)d_in[8];
    const float* b2  = (const float*)d_in[9];
    const float* Wm1 = (const float*)d_in[10];
    const float* bm1 = (const float*)d_in[11];
    const float* Wm2 = (const float*)d_in[12];
    const float* bm2 = (const float*)d_in[13];
    float* out = (float*)d_out;

    static float *hA = nullptr, *hB = nullptr, *agg = nullptr;
    if (!hA) {
        cudaGetSymbolAddress((void**)&hA,  g_hA);
        cudaGetSymbolAddress((void**)&hB,  g_hB);
        cudaGetSymbolAddress((void**)&agg, g_agg);
        cudaFuncSetAttribute(gemm_relu_kernel,
                             cudaFuncAttributeMaxDynamicSharedMemorySize,
                             (128 * 128 + 128 * ASM_STRIDE) * (int)sizeof(float));
    }
    size_t smem = (128 * 128 + 128 * ASM_STRIDE) * sizeof(float);

    init_kernel<<<CDIV(Nn, 256), 256>>>();
    degree_kernel<<<CDIV(Ee, 256), 256>>>(src, dst);
    norm_kernel<<<CDIV(Nn, 256), 256>>>();
    scan_block_kernel<<<NB_SCAN, 1024>>>();
    scan_partials_kernel<<<1, 128>>>();
    add_off_kernel<<<CDIV(Nn + 1, 256), 256>>>();
    bucket_kernel<<<CDIV(Ee, 256), 256>>>(src, dst);

    int agg_blocks = CDIV(Nn * 32, 256);
    int gemm_blocks = CDIV(Nn, BM);

    agg_kernel<<<agg_blocks, 256>>>(x, agg);
    gemm_relu_kernel<<<gemm_blocks, 256, smem>>>(agg, W0, b0, hA);
    agg_kernel<<<agg_blocks, 256>>>(hA, agg);
    gemm_relu_kernel<<<gemm_blocks, 256, smem>>>(agg, W1, b1, hB);
    agg_kernel<<<agg_blocks, 256>>>(hB, agg);
    gemm_relu_kernel<<<gemm_blocks, 256, smem>>>(agg, W2, b2, hA);

    readout_kernel<<<CDIV(CDIV(Nn, 16) * 32, 256), 256>>>(hA, n2g);
    mlp_kernel<<<Gg, Hh>>>(Wm1, bm1, Wm2, bm2, out);
}